// round 1
// baseline (speedup 1.0000x reference)
#include <cuda_runtime.h>
#include <math.h>

#define D_MODEL   2048
#define KV_DIM    512
#define HEAD_DIM  64
#define NUM_HEADS 32
#define NUM_GROUPS 8
#define BATCH     2
#define SEQ       2048
#define M_TOT     (BATCH*SEQ)   // 4096
#define QB        64
#define SPAD      68

// Scratch (allocation-free rule: __device__ globals)
__device__ float g_Q [M_TOT * (size_t)D_MODEL];
__device__ float g_K [M_TOT * (size_t)KV_DIM];
__device__ float g_V [M_TOT * (size_t)KV_DIM];
__device__ float g_AO[M_TOT * (size_t)D_MODEL];

// ---------------------------------------------------------------------------
// C[M,N] = A[M,K] @ W[K,N] + bias[N]
// 128x128 tile, BK=8, 256 threads, 8x8 per thread.
// ---------------------------------------------------------------------------
__global__ __launch_bounds__(256) void sgemm_bias(
    const float* __restrict__ A, const float* __restrict__ W,
    const float* __restrict__ bias, float* __restrict__ C,
    int M, int N, int K)
{
    __shared__ float As[8][128];
    __shared__ float Bs[8][128];

    const int tid = threadIdx.x;
    const int tx  = tid & 15;       // 0..15 -> N direction
    const int ty  = tid >> 4;       // 0..15 -> M direction
    const int rowBase = blockIdx.y * 128;
    const int colBase = blockIdx.x * 128;

    const int arow = tid >> 1;          // 0..127
    const int acol = (tid & 1) * 4;     // 0 or 4
    const int brow = tid >> 5;          // 0..7
    const int bcol = (tid & 31) * 4;    // 0..124

    float acc[8][8];
#pragma unroll
    for (int i = 0; i < 8; i++)
#pragma unroll
        for (int j = 0; j < 8; j++) acc[i][j] = 0.f;

    for (int kt = 0; kt < K; kt += 8) {
        float4 av = *reinterpret_cast<const float4*>(
            A + (size_t)(rowBase + arow) * K + kt + acol);
        As[acol + 0][arow] = av.x;
        As[acol + 1][arow] = av.y;
        As[acol + 2][arow] = av.z;
        As[acol + 3][arow] = av.w;
        *reinterpret_cast<float4*>(&Bs[brow][bcol]) =
            *reinterpret_cast<const float4*>(
                W + (size_t)(kt + brow) * N + colBase + bcol);
        __syncthreads();

#pragma unroll
        for (int kk = 0; kk < 8; kk++) {
            float a[8], b[8];
            *reinterpret_cast<float4*>(&a[0]) = *reinterpret_cast<float4*>(&As[kk][ty * 8]);
            *reinterpret_cast<float4*>(&a[4]) = *reinterpret_cast<float4*>(&As[kk][ty * 8 + 4]);
            *reinterpret_cast<float4*>(&b[0]) = *reinterpret_cast<float4*>(&Bs[kk][tx * 8]);
            *reinterpret_cast<float4*>(&b[4]) = *reinterpret_cast<float4*>(&Bs[kk][tx * 8 + 4]);
#pragma unroll
            for (int i = 0; i < 8; i++)
#pragma unroll
                for (int j = 0; j < 8; j++)
                    acc[i][j] = fmaf(a[i], b[j], acc[i][j]);
        }
        __syncthreads();
    }

#pragma unroll
    for (int i = 0; i < 8; i++) {
        int row = rowBase + ty * 8 + i;
#pragma unroll
        for (int j4 = 0; j4 < 8; j4 += 4) {
            int col = colBase + tx * 8 + j4;
            float4 o;
            o.x = acc[i][j4 + 0] + bias[col + 0];
            o.y = acc[i][j4 + 1] + bias[col + 1];
            o.z = acc[i][j4 + 2] + bias[col + 2];
            o.w = acc[i][j4 + 3] + bias[col + 3];
            *reinterpret_cast<float4*>(C + (size_t)row * N + col) = o;
        }
    }
}

// ---------------------------------------------------------------------------
// Flash-style GQA attention: one CTA = 64 query rows of one (batch, head).
// Q pre-scaled by 1/sqrt(d). Online softmax over 32 key tiles of 64.
// ---------------------------------------------------------------------------
__global__ __launch_bounds__(256) void gqa_flash(
    const float* __restrict__ Q, const float* __restrict__ Kp,
    const float* __restrict__ Vp, float* __restrict__ AO)
{
    extern __shared__ float sm[];
    float* QsT = sm;                    // [64][SPAD]  QsT[d][r]
    float* KsT = QsT + 64 * SPAD;       // [64][SPAD]  KsT[d][t]
    float* Vs  = KsT + 64 * SPAD;       // [64][SPAD]  Vs[t][c]
    float* Ss  = Vs  + 64 * SPAD;       // [64][SPAD]  scores / probs
    float* m_s = Ss  + 64 * SPAD;       // [64]
    float* l_s = m_s + 64;              // [64]
    float* c_s = l_s + 64;              // [64]

    const int tid = threadIdx.x;
    const int tx = tid & 15, ty = tid >> 4;
    const int r0 = ty * 4, c0 = tx * 4;

    const int qblk = blockIdx.x;
    const int head = blockIdx.y;
    const int b    = blockIdx.z;
    const int g    = head >> 2;   // HPG = 4

    const float* Qbase = Q  + ((size_t)(b * SEQ + qblk * QB)) * D_MODEL + head * HEAD_DIM;
    const float* Kbase = Kp + ((size_t)(b * SEQ)) * KV_DIM + g * HEAD_DIM;
    const float* Vbase = Vp + ((size_t)(b * SEQ)) * KV_DIM + g * HEAD_DIM;

    for (int idx = tid; idx < QB * HEAD_DIM; idx += 256) {
        int r = idx >> 6, d = idx & 63;
        QsT[d * SPAD + r] = Qbase[(size_t)r * D_MODEL + d] * 0.125f;
    }
    if (tid < QB) { m_s[tid] = -1e30f; l_s[tid] = 0.f; }

    float acc[4][4];
#pragma unroll
    for (int i = 0; i < 4; i++)
#pragma unroll
        for (int j = 0; j < 4; j++) acc[i][j] = 0.f;

    __syncthreads();

    for (int jb = 0; jb < SEQ / QB; jb++) {
        const float* Kt = Kbase + (size_t)jb * QB * KV_DIM;
        const float* Vt = Vbase + (size_t)jb * QB * KV_DIM;
        for (int idx = tid; idx < QB * HEAD_DIM; idx += 256) {
            int r = idx >> 6, d = idx & 63;
            KsT[d * SPAD + r] = Kt[(size_t)r * KV_DIM + d];
            Vs [r * SPAD + d] = Vt[(size_t)r * KV_DIM + d];
        }
        __syncthreads();

        // S = Q @ K^T (scaled)
        float s[4][4];
#pragma unroll
        for (int i = 0; i < 4; i++)
#pragma unroll
            for (int j = 0; j < 4; j++) s[i][j] = 0.f;

#pragma unroll 8
        for (int d = 0; d < HEAD_DIM; d++) {
            float4 qa = *reinterpret_cast<float4*>(&QsT[d * SPAD + r0]);
            float4 kb = *reinterpret_cast<float4*>(&KsT[d * SPAD + c0]);
            float qv[4] = {qa.x, qa.y, qa.z, qa.w};
            float kv[4] = {kb.x, kb.y, kb.z, kb.w};
#pragma unroll
            for (int i = 0; i < 4; i++)
#pragma unroll
                for (int j = 0; j < 4; j++)
                    s[i][j] = fmaf(qv[i], kv[j], s[i][j]);
        }
#pragma unroll
        for (int i = 0; i < 4; i++) {
            float4 o = {s[i][0], s[i][1], s[i][2], s[i][3]};
            *reinterpret_cast<float4*>(&Ss[(r0 + i) * SPAD + c0]) = o;
        }
        __syncthreads();

        // per-row online softmax (64 row-owner threads)
        if (tid < QB) {
            int r = tid;
            float mold = m_s[r];
            float mx = mold;
            float* srow = &Ss[r * SPAD];
#pragma unroll 8
            for (int c = 0; c < QB; c++) mx = fmaxf(mx, srow[c]);
            float corr = __expf(mold - mx);
            float lsum = 0.f;
#pragma unroll 8
            for (int c = 0; c < QB; c++) {
                float p = __expf(srow[c] - mx);
                srow[c] = p;
                lsum += p;
            }
            l_s[r] = l_s[r] * corr + lsum;
            m_s[r] = mx;
            c_s[r] = corr;
        }
        __syncthreads();

        // O = O*corr + P @ V
#pragma unroll
        for (int i = 0; i < 4; i++) {
            float cr = c_s[r0 + i];
#pragma unroll
            for (int j = 0; j < 4; j++) acc[i][j] *= cr;
        }
#pragma unroll 8
        for (int t = 0; t < QB; t++) {
            float4 v = *reinterpret_cast<float4*>(&Vs[t * SPAD + c0]);
            float p[4] = {Ss[(r0 + 0) * SPAD + t], Ss[(r0 + 1) * SPAD + t],
                          Ss[(r0 + 2) * SPAD + t], Ss[(r0 + 3) * SPAD + t]};
#pragma unroll
            for (int i = 0; i < 4; i++) {
                acc[i][0] = fmaf(p[i], v.x, acc[i][0]);
                acc[i][1] = fmaf(p[i], v.y, acc[i][1]);
                acc[i][2] = fmaf(p[i], v.z, acc[i][2]);
                acc[i][3] = fmaf(p[i], v.w, acc[i][3]);
            }
        }
        __syncthreads();
    }

#pragma unroll
    for (int i = 0; i < 4; i++) {
        float inv = 1.f / l_s[r0 + i];
        size_t row = (size_t)(b * SEQ + qblk * QB + r0 + i);
        float4 o = {acc[i][0] * inv, acc[i][1] * inv, acc[i][2] * inv, acc[i][3] * inv};
        *reinterpret_cast<float4*>(AO + row * D_MODEL + head * HEAD_DIM + c0) = o;
    }
}

// ---------------------------------------------------------------------------
extern "C" void kernel_launch(void* const* d_in, const int* in_sizes, int n_in,
                              void* d_out, int out_size)
{
    (void)in_sizes; (void)n_in; (void)out_size;
    const float* q  = (const float*)d_in[0];
    const float* k  = (const float*)d_in[1];
    const float* v  = (const float*)d_in[2];
    const float* Wq = (const float*)d_in[3];
    const float* bq = (const float*)d_in[4];
    const float* Wk = (const float*)d_in[5];
    const float* bk = (const float*)d_in[6];
    const float* Wv = (const float*)d_in[7];
    const float* bv = (const float*)d_in[8];
    const float* Wo = (const float*)d_in[9];
    const float* bo = (const float*)d_in[10];
    float* out = (float*)d_out;

    float *gQ, *gK, *gV, *gAO;
    cudaGetSymbolAddress((void**)&gQ,  g_Q);
    cudaGetSymbolAddress((void**)&gK,  g_K);
    cudaGetSymbolAddress((void**)&gV,  g_V);
    cudaGetSymbolAddress((void**)&gAO, g_AO);

    const size_t flash_smem = (4 * 64 * SPAD + 3 * 64) * sizeof(float);  // ~70.4 KB
    cudaFuncSetAttribute(gqa_flash, cudaFuncAttributeMaxDynamicSharedMemorySize,
                         (int)flash_smem);

    dim3 blk(256);
    // projections
    sgemm_bias<<<dim3(D_MODEL / 128, M_TOT / 128), blk>>>(q, Wq, bq, gQ, M_TOT, D_MODEL, D_MODEL);
    sgemm_bias<<<dim3(KV_DIM  / 128, M_TOT / 128), blk>>>(k, Wk, bk, gK, M_TOT, KV_DIM,  D_MODEL);
    sgemm_bias<<<dim3(KV_DIM  / 128, M_TOT / 128), blk>>>(v, Wv, bv, gV, M_TOT, KV_DIM,  D_MODEL);
    // attention
    gqa_flash<<<dim3(SEQ / QB, NUM_HEADS, BATCH), blk, flash_smem>>>(gQ, gK, gV, gAO);
    // output projection
    sgemm_bias<<<dim3(D_MODEL / 128, M_TOT / 128), blk>>>(gAO, Wo, bo, out, M_TOT, D_MODEL, D_MODEL);
}

// round 2
// speedup vs baseline: 1.7861x; 1.7861x over previous
#include <cuda_runtime.h>
#include <cuda_bf16.h>
#include <math.h>
#include <stdint.h>

#define D_MODEL   2048
#define KV_DIM    512
#define HEAD_DIM  64
#define NUM_HEADS 32
#define BATCH     2
#define SEQ       2048
#define M_TOT     (BATCH*SEQ)   // 4096
#define K3        (3*D_MODEL)   // 6144 split-K

// ---------------- scratch (__device__ globals; no allocation) ---------------
__device__ __nv_bfloat16 s_qi[(size_t)M_TOT * K3];
__device__ __nv_bfloat16 s_ki[(size_t)M_TOT * K3];
__device__ __nv_bfloat16 s_vi[(size_t)M_TOT * K3];
__device__ __nv_bfloat16 s_ao[(size_t)M_TOT * K3];
__device__ __nv_bfloat16 s_wq[(size_t)K3 * D_MODEL];
__device__ __nv_bfloat16 s_wk[(size_t)K3 * KV_DIM];
__device__ __nv_bfloat16 s_wv[(size_t)K3 * KV_DIM];
__device__ __nv_bfloat16 s_wo[(size_t)K3 * D_MODEL];
__device__ float g_Q [(size_t)M_TOT * D_MODEL];
__device__ float g_K [(size_t)M_TOT * KV_DIM];
__device__ float g_V [(size_t)M_TOT * KV_DIM];
__device__ float g_AO[(size_t)M_TOT * D_MODEL];

// ------------------------------ helpers -------------------------------------
__device__ __forceinline__ uint32_t sptr(const void* p) {
    return (uint32_t)__cvta_generic_to_shared(p);
}
__device__ __forceinline__ void cp16(void* dst, const void* src) {
    asm volatile("cp.async.cg.shared.global [%0], [%1], 16;"
                 :: "r"(sptr(dst)), "l"(src));
}
__device__ __forceinline__ void cp_commit() { asm volatile("cp.async.commit_group;"); }
template<int N_> __device__ __forceinline__ void cp_wait() {
    asm volatile("cp.async.wait_group %0;" :: "n"(N_));
}
__device__ __forceinline__ void ldmA(uint32_t* r, uint32_t a) {
    asm volatile("ldmatrix.sync.aligned.m8n8.x4.shared.b16 {%0,%1,%2,%3}, [%4];"
                 : "=r"(r[0]), "=r"(r[1]), "=r"(r[2]), "=r"(r[3]) : "r"(a));
}
__device__ __forceinline__ void ldmBT(uint32_t* r, uint32_t a) {
    asm volatile("ldmatrix.sync.aligned.m8n8.x4.trans.shared.b16 {%0,%1,%2,%3}, [%4];"
                 : "=r"(r[0]), "=r"(r[1]), "=r"(r[2]), "=r"(r[3]) : "r"(a));
}
__device__ __forceinline__ void mma16816(float* c, const uint32_t* a, const uint32_t* b) {
    asm volatile("mma.sync.aligned.m16n8k16.row.col.f32.bf16.bf16.f32 "
                 "{%0,%1,%2,%3}, {%4,%5,%6,%7}, {%8,%9}, {%0,%1,%2,%3};"
                 : "+f"(c[0]), "+f"(c[1]), "+f"(c[2]), "+f"(c[3])
                 : "r"(a[0]), "r"(a[1]), "r"(a[2]), "r"(a[3]), "r"(b[0]), "r"(b[1]));
}
__device__ __forceinline__ void split2(float x, __nv_bfloat16& hi, __nv_bfloat16& lo) {
    hi = __float2bfloat16(x);
    lo = __float2bfloat16(x - __bfloat162float(hi));
}

// ------------------------- split conversion kernels -------------------------
// Activations: X[M][2048] -> Y[M][6144] with per-row segments (hi, hi, lo)
__global__ void split_act2048(const float* __restrict__ X, __nv_bfloat16* __restrict__ Y) {
    size_t n = (size_t)M_TOT * D_MODEL;
    for (size_t i = (size_t)blockIdx.x * blockDim.x + threadIdx.x; i < n;
         i += (size_t)gridDim.x * blockDim.x) {
        size_t m = i >> 11, k = i & 2047;
        __nv_bfloat16 hi, lo; split2(X[i], hi, lo);
        __nv_bfloat16* y = Y + m * (size_t)K3;
        y[k] = hi; y[2048 + k] = hi; y[4096 + k] = lo;
    }
}
// Weights: W[K][N] -> Y[3K][N] with row blocks (hi, lo, hi)
__global__ void split_wgt(const float* __restrict__ X, __nv_bfloat16* __restrict__ Y, size_t KN) {
    for (size_t i = (size_t)blockIdx.x * blockDim.x + threadIdx.x; i < KN;
         i += (size_t)gridDim.x * blockDim.x) {
        __nv_bfloat16 hi, lo; split2(X[i], hi, lo);
        Y[i] = hi; Y[KN + i] = lo; Y[2 * KN + i] = hi;
    }
}

// --------------------------- split-bf16 GEMM --------------------------------
// C[M][N] = A'[M][K3] * B'[K3][N] + bias ; 128x128x32 tiles, 256 thr, HMMA.
#define GBM 128
#define GBN 128
#define GBK 32
#define ASTR 40    // bf16 elems (80B rows, 16B aligned, conflict-free ldmatrix)
#define BSTR 136   // 272B rows

__global__ __launch_bounds__(256) void gemm_split_bias(
    const __nv_bfloat16* __restrict__ A, const __nv_bfloat16* __restrict__ B,
    const float* __restrict__ bias, float* __restrict__ C,
    int M, int N, int Kt)
{
    __shared__ __nv_bfloat16 As[2][GBM * ASTR];
    __shared__ __nv_bfloat16 Bs[2][GBK * BSTR];

    const int tid = threadIdx.x, lane = tid & 31, wid = tid >> 5;
    const int wm = wid >> 2, wn = wid & 3;          // warp tile 64x32
    const int rowBase = blockIdx.y * GBM, colBase = blockIdx.x * GBN;

    float acc[4][4][4];
#pragma unroll
    for (int a = 0; a < 4; a++)
#pragma unroll
        for (int b = 0; b < 4; b++)
#pragma unroll
            for (int c = 0; c < 4; c++) acc[a][b][c] = 0.f;

    auto loadTiles = [&](int s, int kt) {
#pragma unroll
        for (int h = 0; h < 2; h++) {
            int c = tid + h * 256;
            cp16(&As[s][(c >> 2) * ASTR + (c & 3) * 8],
                 &A[(size_t)(rowBase + (c >> 2)) * Kt + kt + (c & 3) * 8]);
        }
#pragma unroll
        for (int h = 0; h < 2; h++) {
            int c = tid + h * 256;
            cp16(&Bs[s][(c >> 4) * BSTR + (c & 15) * 8],
                 &B[(size_t)(kt + (c >> 4)) * N + colBase + (c & 15) * 8]);
        }
    };

    const int niter = Kt / GBK;
    loadTiles(0, 0); cp_commit();

    for (int t = 0; t < niter; t++) {
        const int cur = t & 1;
        if (t + 1 < niter) { loadTiles(1 - cur, (t + 1) * GBK); cp_commit(); cp_wait<1>(); }
        else cp_wait<0>();
        __syncthreads();

        const __nv_bfloat16* Ab = As[cur];
        const __nv_bfloat16* Bb = Bs[cur];
#pragma unroll
        for (int kk = 0; kk < GBK; kk += 16) {
            uint32_t af[4][4], bf[2][4];
#pragma unroll
            for (int mi = 0; mi < 4; mi++)
                ldmA(af[mi], sptr(&Ab[(wm * 64 + mi * 16 + (lane & 15)) * ASTR
                                      + kk + 8 * (lane >> 4)]));
#pragma unroll
            for (int j = 0; j < 2; j++)
                ldmBT(bf[j], sptr(&Bb[(kk + (lane & 15)) * BSTR
                                      + wn * 32 + j * 16 + 8 * (lane >> 4)]));
#pragma unroll
            for (int mi = 0; mi < 4; mi++)
#pragma unroll
                for (int nj = 0; nj < 4; nj++)
                    mma16816(acc[mi][nj], af[mi], &bf[nj >> 1][(nj & 1) * 2]);
        }
        __syncthreads();
    }

#pragma unroll
    for (int mi = 0; mi < 4; mi++) {
        int row0 = rowBase + wm * 64 + mi * 16 + (lane >> 2);
#pragma unroll
        for (int nj = 0; nj < 4; nj++) {
            int col = colBase + wn * 32 + nj * 8 + 2 * (lane & 3);
            float bx = bias[col], by = bias[col + 1];
            float2 o0 = { acc[mi][nj][0] + bx, acc[mi][nj][1] + by };
            float2 o1 = { acc[mi][nj][2] + bx, acc[mi][nj][3] + by };
            *reinterpret_cast<float2*>(C + (size_t)row0 * N + col) = o0;
            *reinterpret_cast<float2*>(C + (size_t)(row0 + 8) * N + col) = o1;
        }
    }
}

// ----------------------- flash attention (split-bf16 mma) -------------------
#define FSTR 72    // bf16 stride (144B, 16B aligned, conflict-free)
#define SSTR 68    // fp32 stride

__global__ __launch_bounds__(256) void gqa_flash_mma(
    const float* __restrict__ Qf, const float* __restrict__ Kf,
    const float* __restrict__ Vf, float* __restrict__ AO)
{
    extern __shared__ char smraw[];
    __nv_bfloat16* Qhi = (__nv_bfloat16*)smraw;
    __nv_bfloat16* Qlo = Qhi + 64 * FSTR;
    __nv_bfloat16* Khi = Qlo + 64 * FSTR;   // [d][t]
    __nv_bfloat16* Klo = Khi + 64 * FSTR;
    __nv_bfloat16* Vhi = Klo + 64 * FSTR;   // [t][c]
    __nv_bfloat16* Vlo = Vhi + 64 * FSTR;
    __nv_bfloat16* Phi = Vlo + 64 * FSTR;   // [r][t]
    __nv_bfloat16* Plo = Phi + 64 * FSTR;
    float* Sf  = (float*)(Plo + 64 * FSTR); // [64][SSTR]
    float* m_s = Sf + 64 * SSTR;
    float* l_s = m_s + 64;
    float* c_s = l_s + 64;

    const int tid = threadIdx.x, lane = tid & 31, wid = tid >> 5;
    const int wm = wid & 3, wn = wid >> 2;          // warp tile 16x32
    const int qblk = blockIdx.x, head = blockIdx.y, b = blockIdx.z;
    const int g = head >> 2;

    // load + scale + split Q tile (64x64)
    const float* Qbase = Qf + ((size_t)(b * SEQ + qblk * 64)) * D_MODEL + head * HEAD_DIM;
    for (int idx = tid; idx < 64 * 64; idx += 256) {
        int r = idx >> 6, d = idx & 63;
        float x = Qbase[(size_t)r * D_MODEL + d] * 0.125f;
        split2(x, Qhi[r * FSTR + d], Qlo[r * FSTR + d]);
    }
    if (tid < 64) { m_s[tid] = -1e30f; l_s[tid] = 0.f; }

    float o[4][4];
#pragma unroll
    for (int i = 0; i < 4; i++)
#pragma unroll
        for (int j = 0; j < 4; j++) o[i][j] = 0.f;

    const int rowa = wm * 16 + (lane >> 2);
    const uint32_t aoff = 8 * (lane >> 4);
    const int arow15 = lane & 15;

    for (int jb = 0; jb < SEQ / 64; jb++) {
        __syncthreads();    // prev iter done with K/V/P tiles
        const float* Kt = Kf + ((size_t)(b * SEQ + jb * 64)) * KV_DIM + g * HEAD_DIM;
        const float* Vt = Vf + ((size_t)(b * SEQ + jb * 64)) * KV_DIM + g * HEAD_DIM;
        for (int idx = tid; idx < 64 * 64; idx += 256) {
            int t = idx >> 6, d = idx & 63;
            float xk = Kt[(size_t)t * KV_DIM + d];
            split2(xk, Khi[d * FSTR + t], Klo[d * FSTR + t]);   // transposed [d][t]
            float xv = Vt[(size_t)t * KV_DIM + d];
            split2(xv, Vhi[t * FSTR + d], Vlo[t * FSTR + d]);
        }
        __syncthreads();

        // S = Q @ K^T  (3-pass split)
        float s[4][4];
#pragma unroll
        for (int i = 0; i < 4; i++)
#pragma unroll
            for (int j = 0; j < 4; j++) s[i][j] = 0.f;

#pragma unroll
        for (int p = 0; p < 3; p++) {
            const __nv_bfloat16* Aseg = (p == 2) ? Qlo : Qhi;
            const __nv_bfloat16* Bseg = (p == 1) ? Klo : Khi;
#pragma unroll
            for (int kk = 0; kk < 64; kk += 16) {
                uint32_t af[4], bf[2][4];
                ldmA(af, sptr(&Aseg[(wm * 16 + arow15) * FSTR + kk + aoff]));
#pragma unroll
                for (int j = 0; j < 2; j++)
                    ldmBT(bf[j], sptr(&Bseg[(kk + arow15) * FSTR + wn * 32 + j * 16 + aoff]));
#pragma unroll
                for (int nj = 0; nj < 4; nj++)
                    mma16816(s[nj], af, &bf[nj >> 1][(nj & 1) * 2]);
            }
        }
        // write S tile
#pragma unroll
        for (int nj = 0; nj < 4; nj++) {
            int col = wn * 32 + nj * 8 + 2 * (lane & 3);
            *reinterpret_cast<float2*>(&Sf[rowa * SSTR + col]) = make_float2(s[nj][0], s[nj][1]);
            *reinterpret_cast<float2*>(&Sf[(rowa + 8) * SSTR + col]) = make_float2(s[nj][2], s[nj][3]);
        }
        __syncthreads();

        // online softmax (row owners)
        if (tid < 64) {
            int r = tid;
            float mold = m_s[r], mx = mold;
            float* srow = &Sf[r * SSTR];
#pragma unroll 8
            for (int c = 0; c < 64; c++) mx = fmaxf(mx, srow[c]);
            float corr = __expf(mold - mx);
            float lsum = 0.f;
#pragma unroll 8
            for (int c = 0; c < 64; c++) {
                float p = __expf(srow[c] - mx);
                srow[c] = p; lsum += p;
            }
            l_s[r] = l_s[r] * corr + lsum;
            m_s[r] = mx;
            c_s[r] = corr;
        }
        __syncthreads();

        // split P
        for (int idx = tid; idx < 64 * 64; idx += 256) {
            int r = idx >> 6, t = idx & 63;
            split2(Sf[r * SSTR + t], Phi[r * FSTR + t], Plo[r * FSTR + t]);
        }
        __syncthreads();

        // O = O*corr + P @ V  (3-pass split)
        {
            float cr0 = c_s[rowa], cr1 = c_s[rowa + 8];
#pragma unroll
            for (int nj = 0; nj < 4; nj++) {
                o[nj][0] *= cr0; o[nj][1] *= cr0;
                o[nj][2] *= cr1; o[nj][3] *= cr1;
            }
        }
#pragma unroll
        for (int p = 0; p < 3; p++) {
            const __nv_bfloat16* Aseg = (p == 2) ? Plo : Phi;
            const __nv_bfloat16* Bseg = (p == 1) ? Vlo : Vhi;
#pragma unroll
            for (int kk = 0; kk < 64; kk += 16) {
                uint32_t af[4], bf[2][4];
                ldmA(af, sptr(&Aseg[(wm * 16 + arow15) * FSTR + kk + aoff]));
#pragma unroll
                for (int j = 0; j < 2; j++)
                    ldmBT(bf[j], sptr(&Bseg[(kk + arow15) * FSTR + wn * 32 + j * 16 + aoff]));
#pragma unroll
                for (int nj = 0; nj < 4; nj++)
                    mma16816(o[nj], af, &bf[nj >> 1][(nj & 1) * 2]);
            }
        }
    }

    // normalize + write
    float il0 = 1.f / l_s[rowa], il1 = 1.f / l_s[rowa + 8];
    size_t row0 = (size_t)(b * SEQ + qblk * 64 + rowa);
#pragma unroll
    for (int nj = 0; nj < 4; nj++) {
        int col = head * HEAD_DIM + wn * 32 + nj * 8 + 2 * (lane & 3);
        float2 o0 = { o[nj][0] * il0, o[nj][1] * il0 };
        float2 o1 = { o[nj][2] * il1, o[nj][3] * il1 };
        *reinterpret_cast<float2*>(AO + row0 * D_MODEL + col) = o0;
        *reinterpret_cast<float2*>(AO + (row0 + 8) * D_MODEL + col) = o1;
    }
}

// -----------------------------------------------------------------------------
extern "C" void kernel_launch(void* const* d_in, const int* in_sizes, int n_in,
                              void* d_out, int out_size)
{
    (void)in_sizes; (void)n_in; (void)out_size;
    const float* q  = (const float*)d_in[0];
    const float* k  = (const float*)d_in[1];
    const float* v  = (const float*)d_in[2];
    const float* Wq = (const float*)d_in[3];
    const float* bq = (const float*)d_in[4];
    const float* Wk = (const float*)d_in[5];
    const float* bk = (const float*)d_in[6];
    const float* Wv = (const float*)d_in[7];
    const float* bv = (const float*)d_in[8];
    const float* Wo = (const float*)d_in[9];
    const float* bo = (const float*)d_in[10];
    float* out = (float*)d_out;

    __nv_bfloat16 *qi, *ki, *vi, *ao, *wq, *wk, *wv, *wo;
    float *gQ, *gK, *gV, *gAO;
    cudaGetSymbolAddress((void**)&qi, s_qi);
    cudaGetSymbolAddress((void**)&ki, s_ki);
    cudaGetSymbolAddress((void**)&vi, s_vi);
    cudaGetSymbolAddress((void**)&ao, s_ao);
    cudaGetSymbolAddress((void**)&wq, s_wq);
    cudaGetSymbolAddress((void**)&wk, s_wk);
    cudaGetSymbolAddress((void**)&wv, s_wv);
    cudaGetSymbolAddress((void**)&wo, s_wo);
    cudaGetSymbolAddress((void**)&gQ,  g_Q);
    cudaGetSymbolAddress((void**)&gK,  g_K);
    cudaGetSymbolAddress((void**)&gV,  g_V);
    cudaGetSymbolAddress((void**)&gAO, g_AO);

    const size_t flash_smem = 8 * 64 * FSTR * sizeof(__nv_bfloat16)
                            + 64 * SSTR * sizeof(float) + 3 * 64 * sizeof(float);
    cudaFuncSetAttribute(gqa_flash_mma, cudaFuncAttributeMaxDynamicSharedMemorySize,
                         (int)flash_smem);

    // split conversions
    split_act2048<<<2048, 256>>>(q, qi);
    split_act2048<<<2048, 256>>>(k, ki);
    split_act2048<<<2048, 256>>>(v, vi);
    split_wgt<<<2048, 256>>>(Wq, wq, (size_t)D_MODEL * D_MODEL);
    split_wgt<<<512,  256>>>(Wk, wk, (size_t)D_MODEL * KV_DIM);
    split_wgt<<<512,  256>>>(Wv, wv, (size_t)D_MODEL * KV_DIM);
    split_wgt<<<2048, 256>>>(Wo, wo, (size_t)D_MODEL * D_MODEL);

    // projections
    gemm_split_bias<<<dim3(D_MODEL / GBN, M_TOT / GBM), 256>>>(qi, wq, bq, gQ, M_TOT, D_MODEL, K3);
    gemm_split_bias<<<dim3(KV_DIM  / GBN, M_TOT / GBM), 256>>>(ki, wk, bk, gK, M_TOT, KV_DIM,  K3);
    gemm_split_bias<<<dim3(KV_DIM  / GBN, M_TOT / GBM), 256>>>(vi, wv, bv, gV, M_TOT, KV_DIM,  K3);

    // attention
    gqa_flash_mma<<<dim3(SEQ / 64, NUM_HEADS, BATCH), 256, flash_smem>>>(gQ, gK, gV, gAO);

    // output projection
    split_act2048<<<2048, 256>>>(gAO, ao);
    gemm_split_bias<<<dim3(D_MODEL / GBN, M_TOT / GBM), 256>>>(ao, wo, bo, out, M_TOT, D_MODEL, K3);
}

// round 3
// speedup vs baseline: 2.0719x; 1.1600x over previous
#include <cuda_runtime.h>
#include <cuda_bf16.h>
#include <math.h>
#include <stdint.h>

#define D_MODEL   2048
#define KV_DIM    512
#define HEAD_DIM  64
#define NUM_HEADS 32
#define BATCH     2
#define SEQ       2048
#define M_TOT     (BATCH*SEQ)   // 4096
#define K3        (3*D_MODEL)   // 6144 (3-pass split-K)

// ---------------- scratch (__device__ globals; no allocation) ---------------
// split inputs (hi/lo pairs)
__device__ __nv_bfloat16 s_qih[(size_t)M_TOT * D_MODEL];
__device__ __nv_bfloat16 s_qil[(size_t)M_TOT * D_MODEL];
__device__ __nv_bfloat16 s_kih[(size_t)M_TOT * D_MODEL];
__device__ __nv_bfloat16 s_kil[(size_t)M_TOT * D_MODEL];
__device__ __nv_bfloat16 s_vih[(size_t)M_TOT * D_MODEL];
__device__ __nv_bfloat16 s_vil[(size_t)M_TOT * D_MODEL];
// split weights
__device__ __nv_bfloat16 s_wqh[(size_t)D_MODEL * D_MODEL];
__device__ __nv_bfloat16 s_wql[(size_t)D_MODEL * D_MODEL];
__device__ __nv_bfloat16 s_wkh[(size_t)D_MODEL * KV_DIM];
__device__ __nv_bfloat16 s_wkl[(size_t)D_MODEL * KV_DIM];
__device__ __nv_bfloat16 s_wvh[(size_t)D_MODEL * KV_DIM];
__device__ __nv_bfloat16 s_wvl[(size_t)D_MODEL * KV_DIM];
__device__ __nv_bfloat16 s_woh[(size_t)D_MODEL * D_MODEL];
__device__ __nv_bfloat16 s_wol[(size_t)D_MODEL * D_MODEL];
// projected tensors (split bf16, attention-ready layouts)
__device__ __nv_bfloat16 g_Qh[(size_t)M_TOT * D_MODEL];           // [m][2048] pre-scaled
__device__ __nv_bfloat16 g_Ql[(size_t)M_TOT * D_MODEL];
__device__ __nv_bfloat16 g_KhT[(size_t)16 * HEAD_DIM * SEQ];      // [bg][d][t]
__device__ __nv_bfloat16 g_KlT[(size_t)16 * HEAD_DIM * SEQ];
__device__ __nv_bfloat16 g_Vh [(size_t)M_TOT * KV_DIM];           // [m][512]
__device__ __nv_bfloat16 g_Vl [(size_t)M_TOT * KV_DIM];
// attention output (split)
__device__ __nv_bfloat16 g_AOh[(size_t)M_TOT * D_MODEL];
__device__ __nv_bfloat16 g_AOl[(size_t)M_TOT * D_MODEL];

// ------------------------------ helpers -------------------------------------
__device__ __forceinline__ uint32_t sptr(const void* p) {
    return (uint32_t)__cvta_generic_to_shared(p);
}
__device__ __forceinline__ void cp16(void* dst, const void* src) {
    asm volatile("cp.async.cg.shared.global [%0], [%1], 16;"
                 :: "r"(sptr(dst)), "l"(src));
}
__device__ __forceinline__ void cp_commit() { asm volatile("cp.async.commit_group;"); }
template<int N_> __device__ __forceinline__ void cp_wait() {
    asm volatile("cp.async.wait_group %0;" :: "n"(N_));
}
__device__ __forceinline__ void ldmA(uint32_t* r, uint32_t a) {
    asm volatile("ldmatrix.sync.aligned.m8n8.x4.shared.b16 {%0,%1,%2,%3}, [%4];"
                 : "=r"(r[0]), "=r"(r[1]), "=r"(r[2]), "=r"(r[3]) : "r"(a));
}
__device__ __forceinline__ void ldmBT(uint32_t* r, uint32_t a) {
    asm volatile("ldmatrix.sync.aligned.m8n8.x4.trans.shared.b16 {%0,%1,%2,%3}, [%4];"
                 : "=r"(r[0]), "=r"(r[1]), "=r"(r[2]), "=r"(r[3]) : "r"(a));
}
__device__ __forceinline__ void mma16816(float* c, const uint32_t* a, const uint32_t* b) {
    asm volatile("mma.sync.aligned.m16n8k16.row.col.f32.bf16.bf16.f32 "
                 "{%0,%1,%2,%3}, {%4,%5,%6,%7}, {%8,%9}, {%0,%1,%2,%3};"
                 : "+f"(c[0]), "+f"(c[1]), "+f"(c[2]), "+f"(c[3])
                 : "r"(a[0]), "r"(a[1]), "r"(a[2]), "r"(a[3]), "r"(b[0]), "r"(b[1]));
}
__device__ __forceinline__ void split2(float x, __nv_bfloat16& hi, __nv_bfloat16& lo) {
    hi = __float2bfloat16(x);
    lo = __float2bfloat16(x - __bfloat162float(hi));
}
__device__ __forceinline__ __nv_bfloat162 mk2(__nv_bfloat16 a, __nv_bfloat16 b) {
    __nv_bfloat162 r; r.x = a; r.y = b; return r;
}

// ------------------------- split conversion kernels -------------------------
__global__ void split_pair(const float* __restrict__ X,
                           __nv_bfloat16* __restrict__ Yh,
                           __nv_bfloat16* __restrict__ Yl, size_t n) {
    for (size_t i = (size_t)blockIdx.x * blockDim.x + threadIdx.x; i < n;
         i += (size_t)gridDim.x * blockDim.x) {
        __nv_bfloat16 hi, lo; split2(X[i], hi, lo);
        Yh[i] = hi; Yl[i] = lo;
    }
}

// --------------------------- split-bf16 GEMM --------------------------------
// C = A'[M][K3] * B'[K3][N] + bias. A segments {hi,hi,lo}, B segments {hi,lo,hi}
// over logical K=2048. 128x128x32 tiles, 256 threads.
// mode: 0 = f32 out; 1 = Q (scale 0.125 + split); 2 = V (split); 3 = K (split + transpose)
#define GBM 128
#define GBN 128
#define GBK 32
#define ASTR 40
#define BSTR 136

__global__ __launch_bounds__(256) void gemm3(
    const __nv_bfloat16* __restrict__ Ahi, const __nv_bfloat16* __restrict__ Alo,
    const __nv_bfloat16* __restrict__ Bhi, const __nv_bfloat16* __restrict__ Blo,
    const float* __restrict__ bias,
    __nv_bfloat16* __restrict__ Chi, __nv_bfloat16* __restrict__ Clo,
    float* __restrict__ Cf, int N, int mode)
{
    __shared__ __nv_bfloat16 As[2][GBM * ASTR];
    __shared__ __nv_bfloat16 Bs[2][GBK * BSTR];

    const int tid = threadIdx.x, lane = tid & 31, wid = tid >> 5;
    const int wm = wid >> 2, wn = wid & 3;
    const int rowBase = blockIdx.y * GBM, colBase = blockIdx.x * GBN;

    float acc[4][4][4];
#pragma unroll
    for (int a = 0; a < 4; a++)
#pragma unroll
        for (int b = 0; b < 4; b++)
#pragma unroll
            for (int c = 0; c < 4; c++) acc[a][b][c] = 0.f;

    auto loadTiles = [&](int s, int kt) {
        const int seg = kt >> 11, koff = kt & 2047;
        const __nv_bfloat16* Ab = (seg < 2) ? Ahi : Alo;
        const __nv_bfloat16* Bb = (seg == 1) ? Blo : Bhi;
#pragma unroll
        for (int h = 0; h < 2; h++) {
            int c = tid + h * 256;
            cp16(&As[s][(c >> 2) * ASTR + (c & 3) * 8],
                 &Ab[(size_t)(rowBase + (c >> 2)) * D_MODEL + koff + (c & 3) * 8]);
        }
#pragma unroll
        for (int h = 0; h < 2; h++) {
            int c = tid + h * 256;
            cp16(&Bs[s][(c >> 4) * BSTR + (c & 15) * 8],
                 &Bb[(size_t)(koff + (c >> 4)) * N + colBase + (c & 15) * 8]);
        }
    };

    const int niter = K3 / GBK;
    loadTiles(0, 0); cp_commit();

    for (int t = 0; t < niter; t++) {
        const int cur = t & 1;
        if (t + 1 < niter) { loadTiles(1 - cur, (t + 1) * GBK); cp_commit(); cp_wait<1>(); }
        else cp_wait<0>();
        __syncthreads();

        const __nv_bfloat16* Ab = As[cur];
        const __nv_bfloat16* Bb = Bs[cur];
#pragma unroll
        for (int kk = 0; kk < GBK; kk += 16) {
            uint32_t af[4][4], bf[2][4];
#pragma unroll
            for (int mi = 0; mi < 4; mi++)
                ldmA(af[mi], sptr(&Ab[(wm * 64 + mi * 16 + (lane & 15)) * ASTR
                                      + kk + 8 * (lane >> 4)]));
#pragma unroll
            for (int j = 0; j < 2; j++)
                ldmBT(bf[j], sptr(&Bb[(kk + (lane & 15)) * BSTR
                                      + wn * 32 + j * 16 + 8 * (lane >> 4)]));
#pragma unroll
            for (int mi = 0; mi < 4; mi++)
#pragma unroll
                for (int nj = 0; nj < 4; nj++)
                    mma16816(acc[mi][nj], af[mi], &bf[nj >> 1][(nj & 1) * 2]);
        }
        __syncthreads();
    }

#pragma unroll
    for (int mi = 0; mi < 4; mi++) {
        int row0 = rowBase + wm * 64 + mi * 16 + (lane >> 2);
#pragma unroll
        for (int nj = 0; nj < 4; nj++) {
            int col = colBase + wn * 32 + nj * 8 + 2 * (lane & 3);
            float bx = bias[col], by = bias[col + 1];
            float v00 = acc[mi][nj][0] + bx, v01 = acc[mi][nj][1] + by;
            float v10 = acc[mi][nj][2] + bx, v11 = acc[mi][nj][3] + by;
            if (mode == 0) {
                *reinterpret_cast<float2*>(Cf + (size_t)row0 * N + col) = make_float2(v00, v01);
                *reinterpret_cast<float2*>(Cf + (size_t)(row0 + 8) * N + col) = make_float2(v10, v11);
            } else {
                if (mode == 1) { v00 *= 0.125f; v01 *= 0.125f; v10 *= 0.125f; v11 *= 0.125f; }
                __nv_bfloat16 h00, l00, h01, l01, h10, l10, h11, l11;
                split2(v00, h00, l00); split2(v01, h01, l01);
                split2(v10, h10, l10); split2(v11, h11, l11);
                if (mode == 3) {
                    // K: scatter transposed [bg][d][t]
                    int b = row0 >> 11, t = row0 & 2047;
                    int g = col >> 6,  d = col & 63;
                    size_t base0 = ((size_t)(b * 8 + g) * 64 + d) * SEQ;
                    size_t base1 = base0 + SEQ;          // d+1 (col+1, same g: col even, d<63)
                    Chi[base0 + t] = h00;       Clo[base0 + t] = l00;
                    Chi[base1 + t] = h01;       Clo[base1 + t] = l01;
                    Chi[base0 + t + 8] = h10;   Clo[base0 + t + 8] = l10;
                    Chi[base1 + t + 8] = h11;   Clo[base1 + t + 8] = l11;
                } else {
                    *reinterpret_cast<__nv_bfloat162*>(Chi + (size_t)row0 * N + col) = mk2(h00, h01);
                    *reinterpret_cast<__nv_bfloat162*>(Clo + (size_t)row0 * N + col) = mk2(l00, l01);
                    *reinterpret_cast<__nv_bfloat162*>(Chi + (size_t)(row0 + 8) * N + col) = mk2(h10, h11);
                    *reinterpret_cast<__nv_bfloat162*>(Clo + (size_t)(row0 + 8) * N + col) = mk2(l10, l11);
                }
            }
        }
    }
}

// ----------------------- flash attention (2 heads / CTA) --------------------
#define FSTR 72
#define SSTR 68

__global__ __launch_bounds__(512) void gqa_flash_mma(
    const __nv_bfloat16* __restrict__ Qh, const __nv_bfloat16* __restrict__ Ql,
    const __nv_bfloat16* __restrict__ KhT, const __nv_bfloat16* __restrict__ KlT,
    const __nv_bfloat16* __restrict__ Vh, const __nv_bfloat16* __restrict__ Vl,
    __nv_bfloat16* __restrict__ AOh, __nv_bfloat16* __restrict__ AOl)
{
    extern __shared__ char smraw[];
    __nv_bfloat16* Qhi = (__nv_bfloat16*)smraw;            // [128][FSTR]
    __nv_bfloat16* Qlo = Qhi + 128 * FSTR;
    __nv_bfloat16* Khi = Qlo + 128 * FSTR;                 // [2][64][FSTR] stages
    __nv_bfloat16* Klo = Khi + 2 * 64 * FSTR;
    __nv_bfloat16* Vhi = Klo + 2 * 64 * FSTR;
    __nv_bfloat16* Vlo = Vhi + 2 * 64 * FSTR;
    __nv_bfloat16* Phi = Vlo + 2 * 64 * FSTR;              // [128][FSTR]
    __nv_bfloat16* Plo = Phi + 128 * FSTR;
    float* Sf  = (float*)(Plo + 128 * FSTR);               // [128][SSTR]
    float* m_s = Sf + 128 * SSTR;
    float* l_s = m_s + 128;
    float* c_s = l_s + 128;

    const int tid = threadIdx.x, lane = tid & 31, wid = tid >> 5;
    const int wm = wid & 7, wn = wid >> 3;                 // 8 row groups x 2 col groups
    const int qblk = blockIdx.x, hp = blockIdx.y, b = blockIdx.z;
    const int g = hp >> 1;
    const size_t bg = (size_t)(b * 8 + g);
    const int g64 = g * 64;

    auto loadKV = [&](int st, int jb) {
        const int c = tid;                                 // 512 chunks per array
        const int r = c >> 3, off8 = (c & 7) * 8;
        size_t ksrc = (bg * 64 + r) * (size_t)SEQ + jb * 64 + off8;
        size_t vsrc = ((size_t)(b * SEQ + jb * 64 + r)) * KV_DIM + g64 + off8;
        __nv_bfloat16* kd = Khi + st * 64 * FSTR + r * FSTR + off8;
        __nv_bfloat16* kl = Klo + st * 64 * FSTR + r * FSTR + off8;
        __nv_bfloat16* vd = Vhi + st * 64 * FSTR + r * FSTR + off8;
        __nv_bfloat16* vl = Vlo + st * 64 * FSTR + r * FSTR + off8;
        cp16(kd, KhT + ksrc);
        cp16(kl, KlT + ksrc);
        cp16(vd, Vh + vsrc);
        cp16(vl, Vl + vsrc);
    };

    // prologue: KV stage 0, then Q
    loadKV(0, 0); cp_commit();
#pragma unroll
    for (int h = 0; h < 2; h++) {
        int c = tid + h * 512;                             // 1024 chunks
        int r = c >> 3, off8 = (c & 7) * 8;
        size_t src = ((size_t)(b * SEQ + qblk * 64 + (r & 63))) * D_MODEL
                   + (hp * 2 + (r >> 6)) * 64 + off8;
        cp16(Qhi + r * FSTR + off8, Qh + src);
        cp16(Qlo + r * FSTR + off8, Ql + src);
    }
    cp_commit();

    if (tid < 128) { m_s[tid] = -1e30f; l_s[tid] = 0.f; }

    float o[4][4];
#pragma unroll
    for (int i = 0; i < 4; i++)
#pragma unroll
        for (int j = 0; j < 4; j++) o[i][j] = 0.f;

    const int rowa = wm * 16 + (lane >> 2);
    const uint32_t aoff = 8 * (lane >> 4);
    const int arow15 = lane & 15;

    for (int jb = 0; jb < SEQ / 64; jb++) {
        const int cur = jb & 1;
        if (jb + 1 < SEQ / 64) { loadKV(1 - cur, jb + 1); cp_commit(); cp_wait<1>(); }
        else cp_wait<0>();
        __syncthreads();

        const __nv_bfloat16* Kc_h = Khi + cur * 64 * FSTR;
        const __nv_bfloat16* Kc_l = Klo + cur * 64 * FSTR;
        const __nv_bfloat16* Vc_h = Vhi + cur * 64 * FSTR;
        const __nv_bfloat16* Vc_l = Vlo + cur * 64 * FSTR;

        // S = Q @ K^T (3-pass)
        float s[4][4];
#pragma unroll
        for (int i = 0; i < 4; i++)
#pragma unroll
            for (int j = 0; j < 4; j++) s[i][j] = 0.f;

#pragma unroll
        for (int p = 0; p < 3; p++) {
            const __nv_bfloat16* Aseg = (p == 2) ? Qlo : Qhi;
            const __nv_bfloat16* Bseg = (p == 1) ? Kc_l : Kc_h;
#pragma unroll
            for (int kk = 0; kk < 64; kk += 16) {
                uint32_t af[4], bf[2][4];
                ldmA(af, sptr(&Aseg[(wm * 16 + arow15) * FSTR + kk + aoff]));
#pragma unroll
                for (int j = 0; j < 2; j++)
                    ldmBT(bf[j], sptr(&Bseg[(kk + arow15) * FSTR + wn * 32 + j * 16 + aoff]));
#pragma unroll
                for (int nj = 0; nj < 4; nj++)
                    mma16816(s[nj], af, &bf[nj >> 1][(nj & 1) * 2]);
            }
        }
#pragma unroll
        for (int nj = 0; nj < 4; nj++) {
            int col = wn * 32 + nj * 8 + 2 * (lane & 3);
            *reinterpret_cast<float2*>(&Sf[rowa * SSTR + col]) = make_float2(s[nj][0], s[nj][1]);
            *reinterpret_cast<float2*>(&Sf[(rowa + 8) * SSTR + col]) = make_float2(s[nj][2], s[nj][3]);
        }
        __syncthreads();

        // online softmax: 4 threads per row
        {
            int r = tid >> 2, i = tid & 3;
            float* srow = &Sf[r * SSTR + i * 16];
            float mold = m_s[r];
            float pm = -1e30f;
#pragma unroll
            for (int c = 0; c < 16; c++) pm = fmaxf(pm, srow[c]);
            pm = fmaxf(pm, __shfl_xor_sync(0xffffffffu, pm, 1));
            pm = fmaxf(pm, __shfl_xor_sync(0xffffffffu, pm, 2));
            float mx = fmaxf(mold, pm);
            float lsum = 0.f;
#pragma unroll
            for (int c = 0; c < 16; c++) {
                float p = __expf(srow[c] - mx);
                srow[c] = p; lsum += p;
            }
            lsum += __shfl_xor_sync(0xffffffffu, lsum, 1);
            lsum += __shfl_xor_sync(0xffffffffu, lsum, 2);
            if (i == 0) {
                float corr = __expf(mold - mx);
                l_s[r] = l_s[r] * corr + lsum;
                m_s[r] = mx;
                c_s[r] = corr;
            }
        }
        __syncthreads();

        // split P
        for (int idx = tid; idx < 128 * 64; idx += 512) {
            int r = idx >> 6, t = idx & 63;
            split2(Sf[r * SSTR + t], Phi[r * FSTR + t], Plo[r * FSTR + t]);
        }
        __syncthreads();

        // O = O*corr + P @ V (3-pass)
        {
            float cr0 = c_s[rowa], cr1 = c_s[rowa + 8];
#pragma unroll
            for (int nj = 0; nj < 4; nj++) {
                o[nj][0] *= cr0; o[nj][1] *= cr0;
                o[nj][2] *= cr1; o[nj][3] *= cr1;
            }
        }
#pragma unroll
        for (int p = 0; p < 3; p++) {
            const __nv_bfloat16* Aseg = (p == 2) ? Plo : Phi;
            const __nv_bfloat16* Bseg = (p == 1) ? Vc_l : Vc_h;
#pragma unroll
            for (int kk = 0; kk < 64; kk += 16) {
                uint32_t af[4], bf[2][4];
                ldmA(af, sptr(&Aseg[(wm * 16 + arow15) * FSTR + kk + aoff]));
#pragma unroll
                for (int j = 0; j < 2; j++)
                    ldmBT(bf[j], sptr(&Bseg[(kk + arow15) * FSTR + wn * 32 + j * 16 + aoff]));
#pragma unroll
                for (int nj = 0; nj < 4; nj++)
                    mma16816(o[nj], af, &bf[nj >> 1][(nj & 1) * 2]);
            }
        }
        __syncthreads();
    }

    // epilogue: normalize + split-write AO
    float il0 = 1.f / l_s[rowa], il1 = 1.f / l_s[rowa + 8];
    int head = hp * 2 + (rowa >> 6);
    size_t m0 = (size_t)(b * SEQ + qblk * 64 + (rowa & 63));
#pragma unroll
    for (int nj = 0; nj < 4; nj++) {
        int col = head * 64 + wn * 32 + nj * 8 + 2 * (lane & 3);
        float v00 = o[nj][0] * il0, v01 = o[nj][1] * il0;
        float v10 = o[nj][2] * il1, v11 = o[nj][3] * il1;
        __nv_bfloat16 h00, l00, h01, l01, h10, l10, h11, l11;
        split2(v00, h00, l00); split2(v01, h01, l01);
        split2(v10, h10, l10); split2(v11, h11, l11);
        *reinterpret_cast<__nv_bfloat162*>(AOh + m0 * D_MODEL + col) = mk2(h00, h01);
        *reinterpret_cast<__nv_bfloat162*>(AOl + m0 * D_MODEL + col) = mk2(l00, l01);
        *reinterpret_cast<__nv_bfloat162*>(AOh + (m0 + 8) * D_MODEL + col) = mk2(h10, h11);
        *reinterpret_cast<__nv_bfloat162*>(AOl + (m0 + 8) * D_MODEL + col) = mk2(l10, l11);
    }
}

// -----------------------------------------------------------------------------
extern "C" void kernel_launch(void* const* d_in, const int* in_sizes, int n_in,
                              void* d_out, int out_size)
{
    (void)in_sizes; (void)n_in; (void)out_size;
    const float* q  = (const float*)d_in[0];
    const float* k  = (const float*)d_in[1];
    const float* v  = (const float*)d_in[2];
    const float* Wq = (const float*)d_in[3];
    const float* bq = (const float*)d_in[4];
    const float* Wk = (const float*)d_in[5];
    const float* bk = (const float*)d_in[6];
    const float* Wv = (const float*)d_in[7];
    const float* bv = (const float*)d_in[8];
    const float* Wo = (const float*)d_in[9];
    const float* bo = (const float*)d_in[10];
    float* out = (float*)d_out;

    __nv_bfloat16 *qih,*qil,*kih,*kil,*vih,*vil;
    __nv_bfloat16 *wqh,*wql,*wkh,*wkl,*wvh,*wvl,*woh,*wol;
    __nv_bfloat16 *Qh,*Ql,*KhT,*KlT,*Vh,*Vl,*AOh,*AOl;
    cudaGetSymbolAddress((void**)&qih, s_qih); cudaGetSymbolAddress((void**)&qil, s_qil);
    cudaGetSymbolAddress((void**)&kih, s_kih); cudaGetSymbolAddress((void**)&kil, s_kil);
    cudaGetSymbolAddress((void**)&vih, s_vih); cudaGetSymbolAddress((void**)&vil, s_vil);
    cudaGetSymbolAddress((void**)&wqh, s_wqh); cudaGetSymbolAddress((void**)&wql, s_wql);
    cudaGetSymbolAddress((void**)&wkh, s_wkh); cudaGetSymbolAddress((void**)&wkl, s_wkl);
    cudaGetSymbolAddress((void**)&wvh, s_wvh); cudaGetSymbolAddress((void**)&wvl, s_wvl);
    cudaGetSymbolAddress((void**)&woh, s_woh); cudaGetSymbolAddress((void**)&wol, s_wol);
    cudaGetSymbolAddress((void**)&Qh,  g_Qh);  cudaGetSymbolAddress((void**)&Ql,  g_Ql);
    cudaGetSymbolAddress((void**)&KhT, g_KhT); cudaGetSymbolAddress((void**)&KlT, g_KlT);
    cudaGetSymbolAddress((void**)&Vh,  g_Vh);  cudaGetSymbolAddress((void**)&Vl,  g_Vl);
    cudaGetSymbolAddress((void**)&AOh, g_AOh); cudaGetSymbolAddress((void**)&AOl, g_AOl);

    const size_t flash_smem =
        (2 * 128 * FSTR + 4 * 2 * 64 * FSTR + 2 * 128 * FSTR) * sizeof(__nv_bfloat16)
        + (128 * SSTR + 3 * 128) * sizeof(float);
    cudaFuncSetAttribute(gqa_flash_mma, cudaFuncAttributeMaxDynamicSharedMemorySize,
                         (int)flash_smem);

    // splits (hi/lo pairs only)
    const size_t nMD = (size_t)M_TOT * D_MODEL;
    const size_t nDD = (size_t)D_MODEL * D_MODEL;
    const size_t nDK = (size_t)D_MODEL * KV_DIM;
    split_pair<<<2048, 256>>>(q, qih, qil, nMD);
    split_pair<<<2048, 256>>>(k, kih, kil, nMD);
    split_pair<<<2048, 256>>>(v, vih, vil, nMD);
    split_pair<<<2048, 256>>>(Wq, wqh, wql, nDD);
    split_pair<<<512,  256>>>(Wk, wkh, wkl, nDK);
    split_pair<<<512,  256>>>(Wv, wvh, wvl, nDK);
    split_pair<<<2048, 256>>>(Wo, woh, wol, nDD);

    // projections with fused split epilogues
    gemm3<<<dim3(D_MODEL / GBN, M_TOT / GBM), 256>>>(qih, qil, wqh, wql, bq,
        Qh, Ql, nullptr, D_MODEL, 1);
    gemm3<<<dim3(KV_DIM / GBN, M_TOT / GBM), 256>>>(kih, kil, wkh, wkl, bk,
        KhT, KlT, nullptr, KV_DIM, 3);
    gemm3<<<dim3(KV_DIM / GBN, M_TOT / GBM), 256>>>(vih, vil, wvh, wvl, bv,
        Vh, Vl, nullptr, KV_DIM, 2);

    // attention (2 heads per CTA)
    gqa_flash_mma<<<dim3(SEQ / 64, NUM_HEADS / 2, BATCH), 512, flash_smem>>>(
        Qh, Ql, KhT, KlT, Vh, Vl, AOh, AOl);

    // output projection
    gemm3<<<dim3(D_MODEL / GBN, M_TOT / GBM), 256>>>(AOh, AOl, woh, wol, bo,
        nullptr, nullptr, out, D_MODEL, 0);
}